// round 15
// baseline (speedup 1.0000x reference)
#include <cuda_runtime.h>
#include <cuda_fp16.h>
#include <math.h>
#include <stdint.h>

// Problem constants (shapes fixed by setup_inputs)
#define Hh 384
#define Ww 384
#define HW (Hh*Ww)          // 147456
#define MAXB 4
#define CC 64               // channels
#define PP 2048             // max positives
#define KCc 20480           // rim candidate pool
#define KNn 10240           // max negatives
#define RAD 5               // dilation radius (kernel 11)
#define NBLK (HW/1024)      // 144 compaction blocks per image
#define NSPLIT 6
#define INV_T 10.0f

// ---- mma tile config ----
#define ROWB 144            // bytes per padded row (72 fp16): conflict-free frags
#define TILE_B (128*ROWB)   // 18432 bytes per tile buffer
// fused sim+pp kernel dynamic smem: 4 tiles
#define LS_AHI 0
#define LS_ALO (TILE_B)
#define LS_BHI (2*TILE_B)
#define LS_BLO (3*TILE_B)
#define FUSE_SMEM (4*TILE_B)           // 73728
// pn loss kernel: A + B
#define PN_SMEM (2*TILE_B)             // 36864

// ------------------------- scratch (device globals) -------------------------
__device__ unsigned char g_fg [MAXB][HW];
__device__ unsigned char g_rim[MAXB][HW];
__device__ int   g_bcnt[MAXB][NBLK][2];
__device__ int   g_boff[MAXB][NBLK][2];
__device__ int   g_tot [MAXB][2];          // [0]=total fg, [1]=total rim
__device__ int   g_pidx[MAXB][PP];
__device__ int   g_cidx[MAXB][KCc];
__device__ __half g_pf_hi[MAXB][PP][CC];
__device__ __half g_pf_lo[MAXB][PP][CC];
__device__ __half g_cf_hi[MAXB][KCc][CC];
__device__ float g_maxsim[MAXB][KCc];
__device__ int   g_nsel[MAXB][KNn];
__device__ int   g_ksel[MAXB];
__device__ float g_partLpp[MAXB][NSPLIT][PP];
__device__ float g_partExp[MAXB][NSPLIT][PP];
__device__ float g_imgloss[MAXB];
__device__ int   g_has[MAXB];
__device__ int   g_done;

// ------------------------- asm helpers ---------------------------------------
__device__ __forceinline__ void mma_fp16(float* d, const uint32_t* a, const uint32_t* b){
    asm volatile(
        "mma.sync.aligned.m16n8k16.row.col.f32.f16.f16.f32 "
        "{%0,%1,%2,%3}, {%4,%5,%6,%7}, {%8,%9}, {%0,%1,%2,%3};"
        : "+f"(d[0]), "+f"(d[1]), "+f"(d[2]), "+f"(d[3])
        : "r"(a[0]), "r"(a[1]), "r"(a[2]), "r"(a[3]), "r"(b[0]), "r"(b[1]));
}
// zero-C variant: writes D fresh (no accumulator reset needed)
__device__ __forceinline__ void mma_fp16_z(float* d, const uint32_t* a, const uint32_t* b){
    asm volatile(
        "mma.sync.aligned.m16n8k16.row.col.f32.f16.f16.f32 "
        "{%0,%1,%2,%3}, {%4,%5,%6,%7}, {%8,%9}, {%10,%10,%10,%10};"
        : "=f"(d[0]), "=f"(d[1]), "=f"(d[2]), "=f"(d[3])
        : "r"(a[0]), "r"(a[1]), "r"(a[2]), "r"(a[3]), "r"(b[0]), "r"(b[1]),
          "f"(0.0f));
}
// paired 2^x on two half values in one MUFU op
__device__ __forceinline__ float2 exp2_pair(float x0, float x1){
    __half2 h = __floats2half2_rn(x0, x1);
    uint32_t hi = *(uint32_t*)&h, ho;
    asm("ex2.approx.f16x2 %0, %1;" : "=r"(ho) : "r"(hi));
    __half2 he = *(__half2*)&ho;
    return __half22float2(he);
}

// ------------------------- fused masks: fg + dilation + rim + count ---------
// Block = 8-row strip (3072 px = 3 compaction blocks); stages fg for the
// strip + 5-row halo, horizontal dilation in smem, then vertical + rim.
__global__ void __launch_bounds__(384) k_mask(const long long* __restrict__ labels){
    int b = blockIdx.y;
    int rbase = blockIdx.x * 8;
    int col = threadIdx.x;           // 0..383
    __shared__ unsigned char sfg[18][Ww];
    __shared__ unsigned char shd[18][Ww];
    __shared__ int scnt[3][2];
    if (col < 6){ scnt[col>>1][col&1] = 0; }

    // stage fg for rows rbase-5 .. rbase+12 (clamped; OOB rows = 0)
    #pragma unroll
    for (int rr = 0; rr < 18; rr++){
        int row = rbase - RAD + rr;
        unsigned char v = 0;
        if (row >= 0 && row < Hh) v = (labels[(size_t)b*HW + row*Ww + col] > 0) ? 1 : 0;
        sfg[rr][col] = v;
    }
    __syncthreads();
    // horizontal dilation for all staged rows
    int lo = col - RAD; if (lo < 0) lo = 0;
    int hi = col + RAD; if (hi > Ww-1) hi = Ww-1;
    #pragma unroll
    for (int rr = 0; rr < 18; rr++){
        unsigned char m = 0;
        for (int c = lo; c <= hi; c++) m |= sfg[rr][c];
        shd[rr][col] = m;
    }
    __syncthreads();
    // vertical dilation + rim + counts for the strip's 8 rows
    int cf[3] = {0,0,0}, cr[3] = {0,0,0};
    #pragma unroll
    for (int r8 = 0; r8 < 8; r8++){
        int row = rbase + r8;
        int rr  = r8 + RAD;
        int vlo = row - RAD; if (vlo < 0) vlo = 0;
        int vhi = row + RAD; if (vhi > Hh-1) vhi = Hh-1;
        unsigned char m = 0;
        for (int r = vlo; r <= vhi; r++) m |= shd[r - (rbase - RAD)][col];
        unsigned char fg = sfg[rr][col];
        unsigned char rim = (m && !fg) ? 1 : 0;
        int p = row*Ww + col;
        g_fg[b][p]  = fg;
        g_rim[b][p] = rim;
        int sub = (r8*Ww + col) >> 10;   // 0..2 within strip
        cf[sub] += fg; cr[sub] += rim;
    }
    __syncthreads();
    #pragma unroll
    for (int s = 0; s < 3; s++){
        if (cf[s]) atomicAdd(&scnt[s][0], cf[s]);
        if (cr[s]) atomicAdd(&scnt[s][1], cr[s]);
    }
    __syncthreads();
    if (col < 6){
        int blk = blockIdx.x*3 + (col>>1);
        g_bcnt[b][blk][col&1] = scnt[col>>1][col&1];
    }
}

// ------------------------- scan (+ reset done counter) ----------------------
__global__ void k_scan(){
    int b = blockIdx.x;
    if (threadIdx.x == 0){
        if (b == 0) g_done = 0;
        int a0 = 0, a1 = 0;
        for (int k = 0; k < NBLK; k++){
            g_boff[b][k][0] = a0; a0 += g_bcnt[b][k][0];
            g_boff[b][k][1] = a1; a1 += g_bcnt[b][k][1];
        }
        g_tot[b][0] = a0; g_tot[b][1] = a1;
    }
}
__global__ void k_scatter(){
    int b = blockIdx.y, blk = blockIdx.x, tid = threadIdx.x;
    int base = blk*1024 + tid*4;
    unsigned char ff[4], rr[4];
    int lf = 0, lr = 0;
    #pragma unroll
    for (int e = 0; e < 4; e++){
        ff[e] = g_fg[b][base+e];  rr[e] = g_rim[b][base+e];
        lf += ff[e]; lr += rr[e];
    }
    __shared__ int sc[256];
    int own = lf | (lr << 16);
    sc[tid] = own;
    __syncthreads();
    for (int off = 1; off < 256; off <<= 1){
        int v = (tid >= off) ? sc[tid-off] : 0;
        __syncthreads();
        sc[tid] += v;
        __syncthreads();
    }
    int ex = sc[tid] - own;
    int offF = g_boff[b][blk][0] + (ex & 0xffff);
    int offR = g_boff[b][blk][1] + (ex >> 16);
    #pragma unroll
    for (int e = 0; e < 4; e++){
        if (ff[e]){ if (offF < PP)  g_pidx[b][offF] = base+e; offF++; }
        if (rr[e]){ if (offR < KCc) g_cidx[b][offR] = base+e; offR++; }
    }
}

// ------------------------- gather + L2 normalize -> fp16 hi/lo ---------------
__global__ void __launch_bounds__(256) k_gather(const float* __restrict__ feat, int B){
    int gw = (blockIdx.x*blockDim.x + threadIdx.x) >> 5;
    int lane = threadIdx.x & 31;
    const int per = PP + KCc;           // 22528
    const int wpi = per/32;             // 704 warps per image
    if (gw >= B*wpi) return;
    int b = gw / wpi;
    int ws = (gw % wpi)*32;
    bool isP = (ws < PP);
    int slot = (isP ? ws : ws - PP) + lane;
    int cnt  = isP ? min(g_tot[b][0], PP) : min(g_tot[b][1], KCc);
    const int* idxArr = isP ? g_pidx[b] : g_cidx[b];
    bool valid = slot < cnt;
    int pix = valid ? idxArr[slot] : 0;
    const float* fp = feat + (size_t)b*CC*HW + pix;
    float v[CC];
    float ss = 0.f;
    #pragma unroll
    for (int c = 0; c < CC; c++){
        float x = __ldg(fp + (size_t)c*HW);
        v[c] = x;
        ss += x*x;
    }
    float inv = valid ? (1.f / fmaxf(sqrtf(ss), 1e-8f)) : 0.f;
    if (isP){
        __half* dh = g_pf_hi[b][slot];
        __half* dl = g_pf_lo[b][slot];
        #pragma unroll
        for (int c = 0; c < CC; c += 2){
            float x0 = v[c]*inv, x1 = v[c+1]*inv;
            __half h0 = __float2half_rn(x0), h1 = __float2half_rn(x1);
            *(__half2*)(dh + c) = __halves2half2(h0, h1);
            *(__half2*)(dl + c) = __halves2half2(
                __float2half_rn(x0 - __half2float(h0)),
                __float2half_rn(x1 - __half2float(h1)));
        }
    } else {
        __half* dh = g_cf_hi[b][slot];
        #pragma unroll
        for (int c = 0; c < CC; c += 2){
            float x0 = v[c]*inv, x1 = v[c+1]*inv;
            *(__half2*)(dh + c) = __halves2half2(__float2half_rn(x0), __float2half_rn(x1));
        }
    }
}

// ------------------------- fused: pp loss CTAs + mining CTAs ----------------
// blockIdx.x < 16  -> pp loss row-tile rt = blockIdx.x  (3-pass compensated)
// blockIdx.x >= 16 -> mining ct = blockIdx.x - 16 (1-pass, reg-prefetch,
//                     zero-C mma, fast-path epilogue)
__global__ void __launch_bounds__(256) k_simpp(){
    int b = blockIdx.y;
    int tid = threadIdx.x, wid = tid >> 5, lane = tid & 31;
    int warpm = wid & 3, warpn = wid >> 2;
    int g = lane >> 2, tig = lane & 3;
    extern __shared__ char sm[];
    int m0 = warpm*32, n0 = warpn*64;
    int nposE = min(g_tot[b][0], PP);

    if (blockIdx.x < 16){
        // ================= pp loss (split 0), 3-pass =================
        int rt = blockIdx.x;
        __shared__ float redL[128][2];
        __shared__ float redE[128][2];

        for (int i = tid; i < 128*8; i += 256){
            int row = i >> 3, q = i & 7;
            int slot = rt*128 + row;
            uint4 vh = make_uint4(0,0,0,0), vl = make_uint4(0,0,0,0);
            if (slot < nposE){
                vh = ((const uint4*)g_pf_hi[b][slot])[q];
                vl = ((const uint4*)g_pf_lo[b][slot])[q];
            }
            *(uint4*)(sm + LS_AHI + row*ROWB + q*16) = vh;
            *(uint4*)(sm + LS_ALO + row*ROWB + q*16) = vl;
        }

        float acc[2][8][4];
        #pragma unroll
        for (int mt = 0; mt < 2; mt++)
            #pragma unroll
            for (int nt = 0; nt < 8; nt++)
                #pragma unroll
                for (int r = 0; r < 4; r++) acc[mt][nt][r] = 0.f;
        float slpp[4] = {0.f,0.f,0.f,0.f};
        float sexp[4] = {0.f,0.f,0.f,0.f};

        for (int chunk = 0; chunk < 16; chunk++){
            int colBase = chunk*128;
            __syncthreads();
            for (int i = tid; i < 128*8; i += 256){
                int row = i >> 3, q = i & 7;
                int jg = colBase + row;
                uint4 vh = make_uint4(0,0,0,0), vl = make_uint4(0,0,0,0);
                if (jg < nposE){
                    vh = ((const uint4*)g_pf_hi[b][jg])[q];
                    vl = ((const uint4*)g_pf_lo[b][jg])[q];
                }
                *(uint4*)(sm + LS_BHI + row*ROWB + q*16) = vh;
                *(uint4*)(sm + LS_BLO + row*ROWB + q*16) = vl;
            }
            __syncthreads();
            #pragma unroll
            for (int ks = 0; ks < 4; ks++){
                int kb = ks*32 + tig*4;
                uint32_t Ah[2][4], Al[2][4];
                #pragma unroll
                for (int mt = 0; mt < 2; mt++){
                    int abase = (m0 + mt*16 + g)*ROWB + kb;
                    Ah[mt][0] = *(uint32_t*)(sm + LS_AHI + abase);
                    Ah[mt][1] = *(uint32_t*)(sm + LS_AHI + abase + 8*ROWB);
                    Ah[mt][2] = *(uint32_t*)(sm + LS_AHI + abase + 16);
                    Ah[mt][3] = *(uint32_t*)(sm + LS_AHI + abase + 8*ROWB + 16);
                    Al[mt][0] = *(uint32_t*)(sm + LS_ALO + abase);
                    Al[mt][1] = *(uint32_t*)(sm + LS_ALO + abase + 8*ROWB);
                    Al[mt][2] = *(uint32_t*)(sm + LS_ALO + abase + 16);
                    Al[mt][3] = *(uint32_t*)(sm + LS_ALO + abase + 8*ROWB + 16);
                }
                #pragma unroll
                for (int nt = 0; nt < 8; nt++){
                    int bbase = (n0 + nt*8 + g)*ROWB + kb;
                    uint32_t Bh[2], Bl[2];
                    Bh[0] = *(uint32_t*)(sm + LS_BHI + bbase);
                    Bh[1] = *(uint32_t*)(sm + LS_BHI + bbase + 16);
                    Bl[0] = *(uint32_t*)(sm + LS_BLO + bbase);
                    Bl[1] = *(uint32_t*)(sm + LS_BLO + bbase + 16);
                    #pragma unroll
                    for (int mt = 0; mt < 2; mt++){
                        mma_fp16(acc[mt][nt], Ah[mt], Bh);
                        mma_fp16(acc[mt][nt], Ah[mt], Bl);
                        mma_fp16(acc[mt][nt], Al[mt], Bh);
                    }
                }
            }
            #pragma unroll
            for (int mt = 0; mt < 2; mt++){
                #pragma unroll
                for (int nt = 0; nt < 8; nt++){
                    int cbase = colBase + n0 + nt*8 + tig*2;
                    #pragma unroll
                    for (int r = 0; r < 4; r++){
                        int jg = cbase + (r & 1);
                        int slot = mt*2 + (r >> 1);
                        int myrow = rt*128 + m0 + mt*16 + g + (r >> 1)*8;
                        float lp = acc[mt][nt][r] * INV_T;
                        if (jg < nposE && jg != myrow){
                            slpp[slot] += lp;
                            sexp[slot] += __expf(lp);
                        }
                        acc[mt][nt][r] = 0.f;
                    }
                }
            }
        }
        #pragma unroll
        for (int s = 0; s < 4; s++){
            slpp[s] += __shfl_xor_sync(0xffffffffu, slpp[s], 1);
            slpp[s] += __shfl_xor_sync(0xffffffffu, slpp[s], 2);
            sexp[s] += __shfl_xor_sync(0xffffffffu, sexp[s], 1);
            sexp[s] += __shfl_xor_sync(0xffffffffu, sexp[s], 2);
        }
        if (tig == 0){
            #pragma unroll
            for (int s = 0; s < 4; s++){
                int lrow = m0 + (s >> 1)*16 + g + (s & 1)*8;
                redL[lrow][warpn] = slpp[s];
                redE[lrow][warpn] = sexp[s];
            }
        }
        __syncthreads();
        if (tid < 128){
            g_partLpp[b][0][rt*128 + tid] = redL[tid][0] + redL[tid][1];
            g_partExp[b][0][rt*128 + tid] = redE[tid][0] + redE[tid][1];
        }
    } else {
        // ============ mining: reg-prefetch + zero-C mma + fast epilogue ============
        int ct = blockIdx.x - 16;
        char* sA = sm;
        char* sB = sm + TILE_B;
        __shared__ float redM[128][2];
        int ncandE = min(g_tot[b][1], KCc);
        bool fullP = (nposE == PP);

        // stage A once + B chunk0
        for (int i = tid; i < 128*8; i += 256){
            int row = i >> 3, q = i & 7;
            int slot = ct*128 + row;
            uint4 v = make_uint4(0,0,0,0);
            if (slot < ncandE) v = ((const uint4*)g_cf_hi[b][slot])[q];
            *(uint4*)(sA + row*ROWB + q*16) = v;
            uint4 v2 = make_uint4(0,0,0,0);
            if (row < nposE) v2 = ((const uint4*)g_pf_hi[b][row])[q];
            *(uint4*)(sB + row*ROWB + q*16) = v2;
        }
        __syncthreads();

        float acc[2][8][4];
        float rowmax[4] = {-INFINITY, -INFINITY, -INFINITY, -INFINITY};

        for (int chunk = 0; chunk < PP/128; chunk++){
            uint4 pref[4];
            bool more = (chunk + 1 < PP/128);
            if (more){
                #pragma unroll
                for (int it = 0; it < 4; it++){
                    int i = tid + it*256;
                    int row = i >> 3, q = i & 7;
                    int slot = (chunk+1)*128 + row;
                    pref[it] = make_uint4(0,0,0,0);
                    if (slot < nposE) pref[it] = ((const uint4*)g_pf_hi[b][slot])[q];
                }
            }
            #pragma unroll
            for (int ks = 0; ks < 4; ks++){
                int kb = ks*32 + tig*4;
                uint32_t Ah[2][4];
                #pragma unroll
                for (int mt = 0; mt < 2; mt++){
                    int abase = (m0 + mt*16 + g)*ROWB + kb;
                    Ah[mt][0] = *(uint32_t*)(sA + abase);
                    Ah[mt][1] = *(uint32_t*)(sA + abase + 8*ROWB);
                    Ah[mt][2] = *(uint32_t*)(sA + abase + 16);
                    Ah[mt][3] = *(uint32_t*)(sA + abase + 8*ROWB + 16);
                }
                #pragma unroll
                for (int nt = 0; nt < 8; nt++){
                    int bbase = (n0 + nt*8 + g)*ROWB + kb;
                    uint32_t Bh[2];
                    Bh[0] = *(uint32_t*)(sB + bbase);
                    Bh[1] = *(uint32_t*)(sB + bbase + 16);
                    #pragma unroll
                    for (int mt = 0; mt < 2; mt++){
                        if (ks == 0) mma_fp16_z(acc[mt][nt], Ah[mt], Bh);
                        else         mma_fp16  (acc[mt][nt], Ah[mt], Bh);
                    }
                }
            }
            int colChunk = chunk*128;
            if (fullP){
                #pragma unroll
                for (int mt = 0; mt < 2; mt++)
                    #pragma unroll
                    for (int nt = 0; nt < 8; nt++)
                        #pragma unroll
                        for (int r = 0; r < 4; r++){
                            int slot = mt*2 + (r >> 1);
                            rowmax[slot] = fmaxf(rowmax[slot], acc[mt][nt][r]);
                        }
            } else {
                #pragma unroll
                for (int mt = 0; mt < 2; mt++){
                    #pragma unroll
                    for (int nt = 0; nt < 8; nt++){
                        int cbase = colChunk + n0 + nt*8 + tig*2;
                        #pragma unroll
                        for (int r = 0; r < 4; r++){
                            int col = cbase + (r & 1);
                            if (col < nposE){
                                int slot = mt*2 + (r >> 1);
                                rowmax[slot] = fmaxf(rowmax[slot], acc[mt][nt][r]);
                            }
                        }
                    }
                }
            }
            if (more){
                __syncthreads();
                #pragma unroll
                for (int it = 0; it < 4; it++){
                    int i = tid + it*256;
                    int row = i >> 3, q = i & 7;
                    *(uint4*)(sB + row*ROWB + q*16) = pref[it];
                }
                __syncthreads();
            }
        }
        #pragma unroll
        for (int s = 0; s < 4; s++){
            rowmax[s] = fmaxf(rowmax[s], __shfl_xor_sync(0xffffffffu, rowmax[s], 1));
            rowmax[s] = fmaxf(rowmax[s], __shfl_xor_sync(0xffffffffu, rowmax[s], 2));
        }
        if (tig == 0){
            #pragma unroll
            for (int s = 0; s < 4; s++){
                int lrow = m0 + (s >> 1)*16 + g + (s & 1)*8;
                redM[lrow][warpn] = rowmax[s];
            }
        }
        __syncthreads();
        if (tid < 128){
            float m = fmaxf(redM[tid][0], redM[tid][1]);
            int slot = ct*128 + tid;
            g_maxsim[b][slot] = (slot < ncandE && nposE > 0) ? m : -INFINITY;
        }
    }
}

// ------------------------- radix top-K select (1024 thr) --------------------
__device__ __forceinline__ unsigned int simkey(int b, int c, int ncandE){
    float v = (c < ncandE) ? g_maxsim[b][c] : -INFINITY;
    unsigned int u = __float_as_uint(v);
    return (u & 0x80000000u) ? ~u : (u | 0x80000000u);
}
__global__ void __launch_bounds__(1024) k_select(){
    int b = blockIdx.x, tid = threadIdx.x;
    __shared__ int hist[256];
    __shared__ int sChosen, sRem;
    __shared__ int scg[1024], sce[1024];
    int nposE  = min(g_tot[b][0], PP);
    int ncandE = min(g_tot[b][1], KCc);
    int nallow = min(5*nposE, KNn);
    int Ksel = min(nallow, ncandE);
    if (nposE == 0) Ksel = 0;
    if (tid == 0) g_ksel[b] = Ksel;
    if (Ksel == 0) return;

    unsigned int prefix = 0, prefMask = 0;
    int remK = Ksel;
    for (int byte = 3; byte >= 0; byte--){
        if (tid < 256) hist[tid] = 0;
        __syncthreads();
        int shift = byte*8;
        for (int c = tid; c < KCc; c += 1024){
            unsigned int k = simkey(b, c, ncandE);
            if ((k & prefMask) == prefix) atomicAdd(&hist[(k >> shift) & 255], 1);
        }
        __syncthreads();
        if (tid == 0){
            int cum = 0, chosen = 0;
            for (int d = 255; d >= 0; d--){
                if (cum + hist[d] >= remK){ chosen = d; break; }
                cum += hist[d];
            }
            sChosen = chosen; sRem = remK - cum;
        }
        __syncthreads();
        prefix  |= ((unsigned int)sChosen) << shift;
        prefMask |= 0xFFu << shift;
        remK = sRem;
        __syncthreads();
    }
    unsigned int T = prefix;
    int begin = tid*20, end = begin + 20;
    int cg = 0, ce = 0;
    for (int c = begin; c < end; c++){
        unsigned int k = simkey(b, c, ncandE);
        if (k > T) cg++; else if (k == T) ce++;
    }
    scg[tid] = cg; sce[tid] = ce;
    __syncthreads();
    for (int off = 1; off < 1024; off <<= 1){
        int a1 = (tid >= off) ? scg[tid-off] : 0;
        int a2 = (tid >= off) ? sce[tid-off] : 0;
        __syncthreads();
        scg[tid] += a1; sce[tid] += a2;
        __syncthreads();
    }
    int gOff = scg[tid] - cg;
    int eOff = sce[tid] - ce;
    int count_gt = scg[1023];
    for (int c = begin; c < end; c++){
        unsigned int k = simkey(b, c, ncandE);
        if (k > T){ g_nsel[b][gOff++] = c; }
        else if (k == T){
            if (eOff < remK) g_nsel[b][count_gt + eOff] = c;
            eOff++;
        }
    }
}

// ------------------------- pn loss: reg-prefetch + paired exp + fast path ---
__global__ void __launch_bounds__(256) k_lossPN(){
    int b = blockIdx.z, rt = blockIdx.x, sp = 1 + blockIdx.y;
    int tid = threadIdx.x, wid = tid >> 5, lane = tid & 31;
    int warpm = wid & 3, warpn = wid >> 2;
    int g = lane >> 2, tig = lane & 3;
    extern __shared__ char sm[];
    char* sA = sm;
    char* sB = sm + TILE_B;
    __shared__ float redE[128][2];
    int nposE = min(g_tot[b][0], PP);
    int Ksel  = g_ksel[b];
    int knBase0 = sp*2048 - PP;
    const float SC = INV_T * 1.44269504f;   // fold temperature into log2e
    bool fullK = (Ksel == KNn);

    // stage A + B chunk0
    for (int i = tid; i < 128*8; i += 256){
        int row = i >> 3, q = i & 7;
        int slot = rt*128 + row;
        uint4 vh = make_uint4(0,0,0,0);
        if (slot < nposE) vh = ((const uint4*)g_pf_hi[b][slot])[q];
        *(uint4*)(sA + row*ROWB + q*16) = vh;
        int kn = knBase0 + row;
        uint4 v2 = make_uint4(0,0,0,0);
        if (kn < Ksel) v2 = ((const uint4*)g_cf_hi[b][g_nsel[b][kn]])[q];
        *(uint4*)(sB + row*ROWB + q*16) = v2;
    }
    __syncthreads();

    float acc[2][8][4];
    float sexp[4] = {0.f,0.f,0.f,0.f};

    int m0 = warpm*32, n0 = warpn*64;
    for (int chunk = 0; chunk < 16; chunk++){
        uint4 pref[4];
        bool more = (chunk + 1 < 16);
        if (more){
            int knB = knBase0 + (chunk+1)*128;
            #pragma unroll
            for (int it = 0; it < 4; it++){
                int i = tid + it*256;
                int row = i >> 3, q = i & 7;
                int kn = knB + row;
                pref[it] = make_uint4(0,0,0,0);
                if (kn < Ksel) pref[it] = ((const uint4*)g_cf_hi[b][g_nsel[b][kn]])[q];
            }
        }
        #pragma unroll
        for (int ks = 0; ks < 4; ks++){
            int kb = ks*32 + tig*4;
            uint32_t Ah[2][4];
            #pragma unroll
            for (int mt = 0; mt < 2; mt++){
                int abase = (m0 + mt*16 + g)*ROWB + kb;
                Ah[mt][0] = *(uint32_t*)(sA + abase);
                Ah[mt][1] = *(uint32_t*)(sA + abase + 8*ROWB);
                Ah[mt][2] = *(uint32_t*)(sA + abase + 16);
                Ah[mt][3] = *(uint32_t*)(sA + abase + 8*ROWB + 16);
            }
            #pragma unroll
            for (int nt = 0; nt < 8; nt++){
                int bbase = (n0 + nt*8 + g)*ROWB + kb;
                uint32_t Bh[2];
                Bh[0] = *(uint32_t*)(sB + bbase);
                Bh[1] = *(uint32_t*)(sB + bbase + 16);
                #pragma unroll
                for (int mt = 0; mt < 2; mt++){
                    if (ks == 0) mma_fp16_z(acc[mt][nt], Ah[mt], Bh);
                    else         mma_fp16  (acc[mt][nt], Ah[mt], Bh);
                }
            }
        }
        int knChunk = knBase0 + chunk*128;
        if (fullK){
            #pragma unroll
            for (int mt = 0; mt < 2; mt++)
                #pragma unroll
                for (int nt = 0; nt < 8; nt++)
                    #pragma unroll
                    for (int h = 0; h < 2; h++){
                        int slot = mt*2 + h;
                        float2 ef = exp2_pair(acc[mt][nt][h*2+0]*SC,
                                              acc[mt][nt][h*2+1]*SC);
                        sexp[slot] += ef.x + ef.y;
                    }
        } else {
            #pragma unroll
            for (int mt = 0; mt < 2; mt++){
                #pragma unroll
                for (int nt = 0; nt < 8; nt++){
                    int cbase = knChunk + n0 + nt*8 + tig*2;
                    #pragma unroll
                    for (int h = 0; h < 2; h++){
                        int slot = mt*2 + h;
                        float2 ef = exp2_pair(acc[mt][nt][h*2+0]*SC,
                                              acc[mt][nt][h*2+1]*SC);
                        if (cbase + 0 < Ksel) sexp[slot] += ef.x;
                        if (cbase + 1 < Ksel) sexp[slot] += ef.y;
                    }
                }
            }
        }
        if (more){
            __syncthreads();
            #pragma unroll
            for (int it = 0; it < 4; it++){
                int i = tid + it*256;
                int row = i >> 3, q = i & 7;
                *(uint4*)(sB + row*ROWB + q*16) = pref[it];
            }
            __syncthreads();
        }
    }
    #pragma unroll
    for (int s = 0; s < 4; s++){
        sexp[s] += __shfl_xor_sync(0xffffffffu, sexp[s], 1);
        sexp[s] += __shfl_xor_sync(0xffffffffu, sexp[s], 2);
    }
    if (tig == 0){
        #pragma unroll
        for (int s = 0; s < 4; s++){
            int lrow = m0 + (s >> 1)*16 + g + (s & 1)*8;
            redE[lrow][warpn] = sexp[s];
        }
    }
    __syncthreads();
    if (tid < 128){
        g_partLpp[b][sp][rt*128 + tid] = 0.f;
        g_partExp[b][sp][rt*128 + tid] = redE[tid][0] + redE[tid][1];
    }
}

// ------------------------- per-image loss + fused final output ---------------
__global__ void k_final(float* out, int B){
    int b = blockIdx.x, tid = threadIdx.x;
    int nposE = min(g_tot[b][0], PP);
    int npairs = nposE - 1;
    float sum = 0.f; int cnt = 0;
    if (npairs > 0){
        for (int r = tid; r < nposE; r += 256){
            float sl = 0.f, se = 0.f;
            #pragma unroll
            for (int sp = 0; sp < NSPLIT; sp++){ sl += g_partLpp[b][sp][r]; se += g_partExp[b][sp][r]; }
            sum += logf(se) - sl/(float)npairs;
            cnt++;
        }
    }
    __shared__ float ssum[256];
    __shared__ int scnt[256];
    ssum[tid] = sum; scnt[tid] = cnt;
    __syncthreads();
    for (int s = 128; s > 0; s >>= 1){
        if (tid < s){ ssum[tid] += ssum[tid+s]; scnt[tid] += scnt[tid+s]; }
        __syncthreads();
    }
    if (tid == 0){
        g_imgloss[b] = (scnt[0] > 0) ? ssum[0]/(float)scnt[0] : 0.f;
        g_has[b] = (scnt[0] > 0) ? 1 : 0;
        __threadfence();
        int t = atomicAdd(&g_done, 1);
        if (t == B-1){
            float s = 0.f; int c = 0;
            for (int bb = 0; bb < B; bb++) if (g_has[bb]){ s += g_imgloss[bb]; c++; }
            out[0] = s / (float)(c > 0 ? c : 1);
        }
    }
}

// ------------------------- launch -------------------------------------------
extern "C" void kernel_launch(void* const* d_in, const int* in_sizes, int n_in,
                              void* d_out, int out_size){
    const float* feat = (const float*)d_in[0];
    const long long* labels = (const long long*)d_in[1];
    int B = in_sizes[1] / HW;
    if (B < 1) B = 1; if (B > MAXB) B = MAXB;

    cudaFuncSetAttribute(k_simpp,  cudaFuncAttributeMaxDynamicSharedMemorySize, FUSE_SMEM);
    cudaFuncSetAttribute(k_lossPN, cudaFuncAttributeMaxDynamicSharedMemorySize, PN_SMEM);

    k_mask   <<<dim3(Hh/8, B), 384>>>(labels);
    k_scan   <<<B, 32>>>();
    k_scatter<<<dim3(NBLK, B), 256>>>();
    int warps = B*(PP + KCc)/32;
    k_gather <<<(warps + 7)/8, 256>>>(feat, B);
    k_simpp  <<<dim3(16 + KCc/128, B), 256, FUSE_SMEM>>>();
    k_select <<<B, 1024>>>();
    k_lossPN <<<dim3(PP/128, NSPLIT-1, B), 256, PN_SMEM>>>();
    k_final  <<<B, 256>>>((float*)d_out, B);
}

// round 16
// speedup vs baseline: 1.0469x; 1.0469x over previous
#include <cuda_runtime.h>
#include <cuda_fp16.h>
#include <math.h>
#include <stdint.h>

// Problem constants (shapes fixed by setup_inputs)
#define Hh 384
#define Ww 384
#define HW (Hh*Ww)          // 147456
#define MAXB 4
#define CC 64               // channels
#define PP 2048             // max positives
#define KCc 20480           // rim candidate pool
#define KNn 10240           // max negatives
#define RAD 5               // dilation radius (kernel 11)
#define NBLK (HW/1024)      // 144 compaction blocks per image
#define NSPLIT 6
#define INV_T 10.0f

// ---- mma tile config ----
#define ROWB 144            // bytes per padded row (72 fp16): conflict-free frags
#define TILE_B (128*ROWB)   // 18432 bytes per tile buffer
// fused sim+pp kernel dynamic smem: 4 tiles
#define LS_AHI 0
#define LS_ALO (TILE_B)
#define LS_BHI (2*TILE_B)
#define LS_BLO (3*TILE_B)
#define FUSE_SMEM (4*TILE_B)           // 73728
// pn loss kernel: A + B
#define PN_SMEM (2*TILE_B)             // 36864

// ------------------------- scratch (device globals) -------------------------
__device__ unsigned char g_fg [MAXB][HW];
__device__ unsigned char g_hd [MAXB][HW];
__device__ unsigned char g_rim[MAXB][HW];
__device__ int   g_bcnt[MAXB][NBLK][2];
__device__ int   g_boff[MAXB][NBLK][2];
__device__ int   g_tot [MAXB][2];          // [0]=total fg, [1]=total rim
__device__ int   g_pidx[MAXB][PP];
__device__ int   g_cidx[MAXB][KCc];
__device__ __half g_pf_hi[MAXB][PP][CC];
__device__ __half g_pf_lo[MAXB][PP][CC];
__device__ __half g_cf_hi[MAXB][KCc][CC];
__device__ float g_maxsim[MAXB][KCc];
__device__ int   g_nsel[MAXB][KNn];
__device__ int   g_ksel[MAXB];
__device__ float g_partLpp[MAXB][NSPLIT][PP];
__device__ float g_partExp[MAXB][NSPLIT][PP];
__device__ float g_imgloss[MAXB];
__device__ int   g_has[MAXB];
__device__ int   g_done;

// ------------------------- asm helpers ---------------------------------------
__device__ __forceinline__ void mma_fp16(float* d, const uint32_t* a, const uint32_t* b){
    asm volatile(
        "mma.sync.aligned.m16n8k16.row.col.f32.f16.f16.f32 "
        "{%0,%1,%2,%3}, {%4,%5,%6,%7}, {%8,%9}, {%0,%1,%2,%3};"
        : "+f"(d[0]), "+f"(d[1]), "+f"(d[2]), "+f"(d[3])
        : "r"(a[0]), "r"(a[1]), "r"(a[2]), "r"(a[3]), "r"(b[0]), "r"(b[1]));
}
// zero-C variant: writes D fresh (no accumulator reset needed)
__device__ __forceinline__ void mma_fp16_z(float* d, const uint32_t* a, const uint32_t* b){
    asm volatile(
        "mma.sync.aligned.m16n8k16.row.col.f32.f16.f16.f32 "
        "{%0,%1,%2,%3}, {%4,%5,%6,%7}, {%8,%9}, {%10,%10,%10,%10};"
        : "=f"(d[0]), "=f"(d[1]), "=f"(d[2]), "=f"(d[3])
        : "r"(a[0]), "r"(a[1]), "r"(a[2]), "r"(a[3]), "r"(b[0]), "r"(b[1]),
          "f"(0.0f));
}
// paired 2^x on two half values in one MUFU op
__device__ __forceinline__ float2 exp2_pair(float x0, float x1){
    __half2 h = __floats2half2_rn(x0, x1);
    uint32_t hi = *(uint32_t*)&h, ho;
    asm("ex2.approx.f16x2 %0, %1;" : "=r"(ho) : "r"(hi));
    __half2 he = *(__half2*)&ho;
    return __half22float2(he);
}

// ------------------------- fused fg + horizontal dilation --------------------
__global__ void __launch_bounds__(128) k_fgh(const long long* __restrict__ labels){
    int b = blockIdx.y, row = blockIdx.x;
    int tid = threadIdx.x;
    __shared__ unsigned char srow[Ww];
    const long long* lab = labels + (size_t)b*HW + row*Ww;
    for (int i = tid; i < Ww; i += 128) srow[i] = (lab[i] > 0) ? 1 : 0;
    __syncthreads();
    unsigned char* fgr = &g_fg[b][row*Ww];
    unsigned char* hdr = &g_hd[b][row*Ww];
    for (int i = tid; i < Ww; i += 128){
        fgr[i] = srow[i];
        int lo = i-RAD; if (lo < 0) lo = 0;
        int hi = i+RAD; if (hi > Ww-1) hi = Ww-1;
        unsigned char m = 0;
        for (int c = lo; c <= hi; c++) m |= srow[c];
        hdr[i] = m;
    }
}

// ------------------------- fused vertical dilation + rim + count ------------
__global__ void __launch_bounds__(256) k_vrim(){
    int b = blockIdx.y, blk = blockIdx.x, tid = threadIdx.x;
    int base = blk*1024 + tid*4;
    int cf = 0, cr = 0;
    #pragma unroll
    for (int e = 0; e < 4; e++){
        int p = base + e;
        int row = p / Ww, col = p % Ww;
        int lo = row-RAD; if (lo < 0) lo = 0;
        int hi = row+RAD; if (hi > Hh-1) hi = Hh-1;
        unsigned char m = 0;
        for (int r = lo; r <= hi; r++) m |= g_hd[b][r*Ww + col];
        unsigned char fg = g_fg[b][p];
        unsigned char rim = (m && !fg) ? 1 : 0;
        g_rim[b][p] = rim;
        cf += fg; cr += rim;
    }
    __shared__ int sf, sr;
    if (tid == 0){ sf = 0; sr = 0; }
    __syncthreads();
    atomicAdd(&sf, cf); atomicAdd(&sr, cr);
    __syncthreads();
    if (tid == 0){ g_bcnt[b][blk][0] = sf; g_bcnt[b][blk][1] = sr; }
}

// ------------------------- scan (+ reset done counter) ----------------------
__global__ void k_scan(){
    int b = blockIdx.x;
    if (threadIdx.x == 0){
        if (b == 0) g_done = 0;
        int a0 = 0, a1 = 0;
        for (int k = 0; k < NBLK; k++){
            g_boff[b][k][0] = a0; a0 += g_bcnt[b][k][0];
            g_boff[b][k][1] = a1; a1 += g_bcnt[b][k][1];
        }
        g_tot[b][0] = a0; g_tot[b][1] = a1;
    }
}
__global__ void k_scatter(){
    int b = blockIdx.y, blk = blockIdx.x, tid = threadIdx.x;
    int base = blk*1024 + tid*4;
    unsigned char ff[4], rr[4];
    int lf = 0, lr = 0;
    #pragma unroll
    for (int e = 0; e < 4; e++){
        ff[e] = g_fg[b][base+e];  rr[e] = g_rim[b][base+e];
        lf += ff[e]; lr += rr[e];
    }
    __shared__ int sc[256];
    int own = lf | (lr << 16);
    sc[tid] = own;
    __syncthreads();
    for (int off = 1; off < 256; off <<= 1){
        int v = (tid >= off) ? sc[tid-off] : 0;
        __syncthreads();
        sc[tid] += v;
        __syncthreads();
    }
    int ex = sc[tid] - own;
    int offF = g_boff[b][blk][0] + (ex & 0xffff);
    int offR = g_boff[b][blk][1] + (ex >> 16);
    #pragma unroll
    for (int e = 0; e < 4; e++){
        if (ff[e]){ if (offF < PP)  g_pidx[b][offF] = base+e; offF++; }
        if (rr[e]){ if (offR < KCc) g_cidx[b][offR] = base+e; offR++; }
    }
}

// ------------------------- gather + L2 normalize -> fp16 hi/lo ---------------
// Warp = 16 slots x 2 channel-halves (lane = half*16 + s). Each thread loads
// 32 channels; partial ss combined via one shfl. Halves the per-thread latency
// chain and doubles warp-level parallelism vs the 64-channel variant.
__global__ void __launch_bounds__(256) k_gather(const float* __restrict__ feat, int B){
    int gw = (blockIdx.x*blockDim.x + threadIdx.x) >> 5;
    int lane = threadIdx.x & 31;
    const int per = PP + KCc;           // 22528
    const int wpi = per/16;             // 1408 warps per image
    if (gw >= B*wpi) return;
    int b = gw / wpi;
    int ws = (gw % wpi)*16;
    int s = lane & 15;
    int half = lane >> 4;               // 0: ch 0..31, 1: ch 32..63
    int slot = ws + s;
    bool isP = (slot < PP);
    int lslot = isP ? slot : slot - PP;
    int cnt  = isP ? min(g_tot[b][0], PP) : min(g_tot[b][1], KCc);
    const int* idxArr = isP ? g_pidx[b] : g_cidx[b];
    bool valid = lslot < cnt;
    int pix = valid ? idxArr[lslot] : 0;
    const float* fp = feat + (size_t)b*CC*HW + (size_t)(half*32)*HW + pix;
    float v[32];
    float ss = 0.f;
    #pragma unroll
    for (int c = 0; c < 32; c++){
        float x = __ldg(fp + (size_t)c*HW);
        v[c] = x;
        ss += x*x;
    }
    ss += __shfl_xor_sync(0xffffffffu, ss, 16);
    float inv = valid ? (1.f / fmaxf(sqrtf(ss), 1e-8f)) : 0.f;
    int cb = half*32;
    if (isP){
        __half* dh = g_pf_hi[b][lslot] + cb;
        __half* dl = g_pf_lo[b][lslot] + cb;
        #pragma unroll
        for (int c = 0; c < 32; c += 2){
            float x0 = v[c]*inv, x1 = v[c+1]*inv;
            __half h0 = __float2half_rn(x0), h1 = __float2half_rn(x1);
            *(__half2*)(dh + c) = __halves2half2(h0, h1);
            *(__half2*)(dl + c) = __halves2half2(
                __float2half_rn(x0 - __half2float(h0)),
                __float2half_rn(x1 - __half2float(h1)));
        }
    } else {
        __half* dh = g_cf_hi[b][lslot] + cb;
        #pragma unroll
        for (int c = 0; c < 32; c += 2){
            float x0 = v[c]*inv, x1 = v[c+1]*inv;
            *(__half2*)(dh + c) = __halves2half2(__float2half_rn(x0), __float2half_rn(x1));
        }
    }
}

// ------------------------- fused: pp loss CTAs + mining CTAs ----------------
// blockIdx.x < 16  -> pp loss row-tile rt = blockIdx.x  (3-pass compensated)
// blockIdx.x >= 16 -> mining ct = blockIdx.x - 16 (1-pass, reg-prefetch,
//                     zero-C mma, fast-path epilogue)
__global__ void __launch_bounds__(256) k_simpp(){
    int b = blockIdx.y;
    int tid = threadIdx.x, wid = tid >> 5, lane = tid & 31;
    int warpm = wid & 3, warpn = wid >> 2;
    int g = lane >> 2, tig = lane & 3;
    extern __shared__ char sm[];
    int m0 = warpm*32, n0 = warpn*64;
    int nposE = min(g_tot[b][0], PP);

    if (blockIdx.x < 16){
        // ================= pp loss (split 0), 3-pass =================
        int rt = blockIdx.x;
        __shared__ float redL[128][2];
        __shared__ float redE[128][2];

        for (int i = tid; i < 128*8; i += 256){
            int row = i >> 3, q = i & 7;
            int slot = rt*128 + row;
            uint4 vh = make_uint4(0,0,0,0), vl = make_uint4(0,0,0,0);
            if (slot < nposE){
                vh = ((const uint4*)g_pf_hi[b][slot])[q];
                vl = ((const uint4*)g_pf_lo[b][slot])[q];
            }
            *(uint4*)(sm + LS_AHI + row*ROWB + q*16) = vh;
            *(uint4*)(sm + LS_ALO + row*ROWB + q*16) = vl;
        }

        float acc[2][8][4];
        #pragma unroll
        for (int mt = 0; mt < 2; mt++)
            #pragma unroll
            for (int nt = 0; nt < 8; nt++)
                #pragma unroll
                for (int r = 0; r < 4; r++) acc[mt][nt][r] = 0.f;
        float slpp[4] = {0.f,0.f,0.f,0.f};
        float sexp[4] = {0.f,0.f,0.f,0.f};

        for (int chunk = 0; chunk < 16; chunk++){
            int colBase = chunk*128;
            __syncthreads();
            for (int i = tid; i < 128*8; i += 256){
                int row = i >> 3, q = i & 7;
                int jg = colBase + row;
                uint4 vh = make_uint4(0,0,0,0), vl = make_uint4(0,0,0,0);
                if (jg < nposE){
                    vh = ((const uint4*)g_pf_hi[b][jg])[q];
                    vl = ((const uint4*)g_pf_lo[b][jg])[q];
                }
                *(uint4*)(sm + LS_BHI + row*ROWB + q*16) = vh;
                *(uint4*)(sm + LS_BLO + row*ROWB + q*16) = vl;
            }
            __syncthreads();
            #pragma unroll
            for (int ks = 0; ks < 4; ks++){
                int kb = ks*32 + tig*4;
                uint32_t Ah[2][4], Al[2][4];
                #pragma unroll
                for (int mt = 0; mt < 2; mt++){
                    int abase = (m0 + mt*16 + g)*ROWB + kb;
                    Ah[mt][0] = *(uint32_t*)(sm + LS_AHI + abase);
                    Ah[mt][1] = *(uint32_t*)(sm + LS_AHI + abase + 8*ROWB);
                    Ah[mt][2] = *(uint32_t*)(sm + LS_AHI + abase + 16);
                    Ah[mt][3] = *(uint32_t*)(sm + LS_AHI + abase + 8*ROWB + 16);
                    Al[mt][0] = *(uint32_t*)(sm + LS_ALO + abase);
                    Al[mt][1] = *(uint32_t*)(sm + LS_ALO + abase + 8*ROWB);
                    Al[mt][2] = *(uint32_t*)(sm + LS_ALO + abase + 16);
                    Al[mt][3] = *(uint32_t*)(sm + LS_ALO + abase + 8*ROWB + 16);
                }
                #pragma unroll
                for (int nt = 0; nt < 8; nt++){
                    int bbase = (n0 + nt*8 + g)*ROWB + kb;
                    uint32_t Bh[2], Bl[2];
                    Bh[0] = *(uint32_t*)(sm + LS_BHI + bbase);
                    Bh[1] = *(uint32_t*)(sm + LS_BHI + bbase + 16);
                    Bl[0] = *(uint32_t*)(sm + LS_BLO + bbase);
                    Bl[1] = *(uint32_t*)(sm + LS_BLO + bbase + 16);
                    #pragma unroll
                    for (int mt = 0; mt < 2; mt++){
                        mma_fp16(acc[mt][nt], Ah[mt], Bh);
                        mma_fp16(acc[mt][nt], Ah[mt], Bl);
                        mma_fp16(acc[mt][nt], Al[mt], Bh);
                    }
                }
            }
            #pragma unroll
            for (int mt = 0; mt < 2; mt++){
                #pragma unroll
                for (int nt = 0; nt < 8; nt++){
                    int cbase = colBase + n0 + nt*8 + tig*2;
                    #pragma unroll
                    for (int r = 0; r < 4; r++){
                        int jg = cbase + (r & 1);
                        int slot = mt*2 + (r >> 1);
                        int myrow = rt*128 + m0 + mt*16 + g + (r >> 1)*8;
                        float lp = acc[mt][nt][r] * INV_T;
                        if (jg < nposE && jg != myrow){
                            slpp[slot] += lp;
                            sexp[slot] += __expf(lp);
                        }
                        acc[mt][nt][r] = 0.f;
                    }
                }
            }
        }
        #pragma unroll
        for (int s = 0; s < 4; s++){
            slpp[s] += __shfl_xor_sync(0xffffffffu, slpp[s], 1);
            slpp[s] += __shfl_xor_sync(0xffffffffu, slpp[s], 2);
            sexp[s] += __shfl_xor_sync(0xffffffffu, sexp[s], 1);
            sexp[s] += __shfl_xor_sync(0xffffffffu, sexp[s], 2);
        }
        if (tig == 0){
            #pragma unroll
            for (int s = 0; s < 4; s++){
                int lrow = m0 + (s >> 1)*16 + g + (s & 1)*8;
                redL[lrow][warpn] = slpp[s];
                redE[lrow][warpn] = sexp[s];
            }
        }
        __syncthreads();
        if (tid < 128){
            g_partLpp[b][0][rt*128 + tid] = redL[tid][0] + redL[tid][1];
            g_partExp[b][0][rt*128 + tid] = redE[tid][0] + redE[tid][1];
        }
    } else {
        // ============ mining: reg-prefetch + zero-C mma + fast epilogue ============
        int ct = blockIdx.x - 16;
        char* sA = sm;
        char* sB = sm + TILE_B;
        __shared__ float redM[128][2];
        int ncandE = min(g_tot[b][1], KCc);
        bool fullP = (nposE == PP);

        // stage A once + B chunk0
        for (int i = tid; i < 128*8; i += 256){
            int row = i >> 3, q = i & 7;
            int slot = ct*128 + row;
            uint4 v = make_uint4(0,0,0,0);
            if (slot < ncandE) v = ((const uint4*)g_cf_hi[b][slot])[q];
            *(uint4*)(sA + row*ROWB + q*16) = v;
            uint4 v2 = make_uint4(0,0,0,0);
            if (row < nposE) v2 = ((const uint4*)g_pf_hi[b][row])[q];
            *(uint4*)(sB + row*ROWB + q*16) = v2;
        }
        __syncthreads();

        float acc[2][8][4];
        float rowmax[4] = {-INFINITY, -INFINITY, -INFINITY, -INFINITY};

        for (int chunk = 0; chunk < PP/128; chunk++){
            uint4 pref[4];
            bool more = (chunk + 1 < PP/128);
            if (more){
                #pragma unroll
                for (int it = 0; it < 4; it++){
                    int i = tid + it*256;
                    int row = i >> 3, q = i & 7;
                    int slot = (chunk+1)*128 + row;
                    pref[it] = make_uint4(0,0,0,0);
                    if (slot < nposE) pref[it] = ((const uint4*)g_pf_hi[b][slot])[q];
                }
            }
            #pragma unroll
            for (int ks = 0; ks < 4; ks++){
                int kb = ks*32 + tig*4;
                uint32_t Ah[2][4];
                #pragma unroll
                for (int mt = 0; mt < 2; mt++){
                    int abase = (m0 + mt*16 + g)*ROWB + kb;
                    Ah[mt][0] = *(uint32_t*)(sA + abase);
                    Ah[mt][1] = *(uint32_t*)(sA + abase + 8*ROWB);
                    Ah[mt][2] = *(uint32_t*)(sA + abase + 16);
                    Ah[mt][3] = *(uint32_t*)(sA + abase + 8*ROWB + 16);
                }
                #pragma unroll
                for (int nt = 0; nt < 8; nt++){
                    int bbase = (n0 + nt*8 + g)*ROWB + kb;
                    uint32_t Bh[2];
                    Bh[0] = *(uint32_t*)(sB + bbase);
                    Bh[1] = *(uint32_t*)(sB + bbase + 16);
                    #pragma unroll
                    for (int mt = 0; mt < 2; mt++){
                        if (ks == 0) mma_fp16_z(acc[mt][nt], Ah[mt], Bh);
                        else         mma_fp16  (acc[mt][nt], Ah[mt], Bh);
                    }
                }
            }
            int colChunk = chunk*128;
            if (fullP){
                #pragma unroll
                for (int mt = 0; mt < 2; mt++)
                    #pragma unroll
                    for (int nt = 0; nt < 8; nt++)
                        #pragma unroll
                        for (int r = 0; r < 4; r++){
                            int slot = mt*2 + (r >> 1);
                            rowmax[slot] = fmaxf(rowmax[slot], acc[mt][nt][r]);
                        }
            } else {
                #pragma unroll
                for (int mt = 0; mt < 2; mt++){
                    #pragma unroll
                    for (int nt = 0; nt < 8; nt++){
                        int cbase = colChunk + n0 + nt*8 + tig*2;
                        #pragma unroll
                        for (int r = 0; r < 4; r++){
                            int col = cbase + (r & 1);
                            if (col < nposE){
                                int slot = mt*2 + (r >> 1);
                                rowmax[slot] = fmaxf(rowmax[slot], acc[mt][nt][r]);
                            }
                        }
                    }
                }
            }
            if (more){
                __syncthreads();
                #pragma unroll
                for (int it = 0; it < 4; it++){
                    int i = tid + it*256;
                    int row = i >> 3, q = i & 7;
                    *(uint4*)(sB + row*ROWB + q*16) = pref[it];
                }
                __syncthreads();
            }
        }
        #pragma unroll
        for (int s = 0; s < 4; s++){
            rowmax[s] = fmaxf(rowmax[s], __shfl_xor_sync(0xffffffffu, rowmax[s], 1));
            rowmax[s] = fmaxf(rowmax[s], __shfl_xor_sync(0xffffffffu, rowmax[s], 2));
        }
        if (tig == 0){
            #pragma unroll
            for (int s = 0; s < 4; s++){
                int lrow = m0 + (s >> 1)*16 + g + (s & 1)*8;
                redM[lrow][warpn] = rowmax[s];
            }
        }
        __syncthreads();
        if (tid < 128){
            float m = fmaxf(redM[tid][0], redM[tid][1]);
            int slot = ct*128 + tid;
            g_maxsim[b][slot] = (slot < ncandE && nposE > 0) ? m : -INFINITY;
        }
    }
}

// ------------------------- radix top-K select (1024 thr) --------------------
__device__ __forceinline__ unsigned int simkey(int b, int c, int ncandE){
    float v = (c < ncandE) ? g_maxsim[b][c] : -INFINITY;
    unsigned int u = __float_as_uint(v);
    return (u & 0x80000000u) ? ~u : (u | 0x80000000u);
}
__global__ void __launch_bounds__(1024) k_select(){
    int b = blockIdx.x, tid = threadIdx.x;
    __shared__ int hist[256];
    __shared__ int sChosen, sRem;
    __shared__ int scg[1024], sce[1024];
    int nposE  = min(g_tot[b][0], PP);
    int ncandE = min(g_tot[b][1], KCc);
    int nallow = min(5*nposE, KNn);
    int Ksel = min(nallow, ncandE);
    if (nposE == 0) Ksel = 0;
    if (tid == 0) g_ksel[b] = Ksel;
    if (Ksel == 0) return;

    unsigned int prefix = 0, prefMask = 0;
    int remK = Ksel;
    for (int byte = 3; byte >= 0; byte--){
        if (tid < 256) hist[tid] = 0;
        __syncthreads();
        int shift = byte*8;
        for (int c = tid; c < KCc; c += 1024){
            unsigned int k = simkey(b, c, ncandE);
            if ((k & prefMask) == prefix) atomicAdd(&hist[(k >> shift) & 255], 1);
        }
        __syncthreads();
        if (tid == 0){
            int cum = 0, chosen = 0;
            for (int d = 255; d >= 0; d--){
                if (cum + hist[d] >= remK){ chosen = d; break; }
                cum += hist[d];
            }
            sChosen = chosen; sRem = remK - cum;
        }
        __syncthreads();
        prefix  |= ((unsigned int)sChosen) << shift;
        prefMask |= 0xFFu << shift;
        remK = sRem;
        __syncthreads();
    }
    unsigned int T = prefix;
    int begin = tid*20, end = begin + 20;
    int cg = 0, ce = 0;
    for (int c = begin; c < end; c++){
        unsigned int k = simkey(b, c, ncandE);
        if (k > T) cg++; else if (k == T) ce++;
    }
    scg[tid] = cg; sce[tid] = ce;
    __syncthreads();
    for (int off = 1; off < 1024; off <<= 1){
        int a1 = (tid >= off) ? scg[tid-off] : 0;
        int a2 = (tid >= off) ? sce[tid-off] : 0;
        __syncthreads();
        scg[tid] += a1; sce[tid] += a2;
        __syncthreads();
    }
    int gOff = scg[tid] - cg;
    int eOff = sce[tid] - ce;
    int count_gt = scg[1023];
    for (int c = begin; c < end; c++){
        unsigned int k = simkey(b, c, ncandE);
        if (k > T){ g_nsel[b][gOff++] = c; }
        else if (k == T){
            if (eOff < remK) g_nsel[b][count_gt + eOff] = c;
            eOff++;
        }
    }
}

// ------------------------- pn loss: reg-prefetch + paired exp + fast path ---
__global__ void __launch_bounds__(256) k_lossPN(){
    int b = blockIdx.z, rt = blockIdx.x, sp = 1 + blockIdx.y;
    int tid = threadIdx.x, wid = tid >> 5, lane = tid & 31;
    int warpm = wid & 3, warpn = wid >> 2;
    int g = lane >> 2, tig = lane & 3;
    extern __shared__ char sm[];
    char* sA = sm;
    char* sB = sm + TILE_B;
    __shared__ float redE[128][2];
    int nposE = min(g_tot[b][0], PP);
    int Ksel  = g_ksel[b];
    int knBase0 = sp*2048 - PP;
    const float SC = INV_T * 1.44269504f;   // fold temperature into log2e
    bool fullK = (Ksel == KNn);

    // stage A + B chunk0
    for (int i = tid; i < 128*8; i += 256){
        int row = i >> 3, q = i & 7;
        int slot = rt*128 + row;
        uint4 vh = make_uint4(0,0,0,0);
        if (slot < nposE) vh = ((const uint4*)g_pf_hi[b][slot])[q];
        *(uint4*)(sA + row*ROWB + q*16) = vh;
        int kn = knBase0 + row;
        uint4 v2 = make_uint4(0,0,0,0);
        if (kn < Ksel) v2 = ((const uint4*)g_cf_hi[b][g_nsel[b][kn]])[q];
        *(uint4*)(sB + row*ROWB + q*16) = v2;
    }
    __syncthreads();

    float acc[2][8][4];
    float sexp[4] = {0.f,0.f,0.f,0.f};

    int m0 = warpm*32, n0 = warpn*64;
    for (int chunk = 0; chunk < 16; chunk++){
        uint4 pref[4];
        bool more = (chunk + 1 < 16);
        if (more){
            int knB = knBase0 + (chunk+1)*128;
            #pragma unroll
            for (int it = 0; it < 4; it++){
                int i = tid + it*256;
                int row = i >> 3, q = i & 7;
                int kn = knB + row;
                pref[it] = make_uint4(0,0,0,0);
                if (kn < Ksel) pref[it] = ((const uint4*)g_cf_hi[b][g_nsel[b][kn]])[q];
            }
        }
        #pragma unroll
        for (int ks = 0; ks < 4; ks++){
            int kb = ks*32 + tig*4;
            uint32_t Ah[2][4];
            #pragma unroll
            for (int mt = 0; mt < 2; mt++){
                int abase = (m0 + mt*16 + g)*ROWB + kb;
                Ah[mt][0] = *(uint32_t*)(sA + abase);
                Ah[mt][1] = *(uint32_t*)(sA + abase + 8*ROWB);
                Ah[mt][2] = *(uint32_t*)(sA + abase + 16);
                Ah[mt][3] = *(uint32_t*)(sA + abase + 8*ROWB + 16);
            }
            #pragma unroll
            for (int nt = 0; nt < 8; nt++){
                int bbase = (n0 + nt*8 + g)*ROWB + kb;
                uint32_t Bh[2];
                Bh[0] = *(uint32_t*)(sB + bbase);
                Bh[1] = *(uint32_t*)(sB + bbase + 16);
                #pragma unroll
                for (int mt = 0; mt < 2; mt++){
                    if (ks == 0) mma_fp16_z(acc[mt][nt], Ah[mt], Bh);
                    else         mma_fp16  (acc[mt][nt], Ah[mt], Bh);
                }
            }
        }
        int knChunk = knBase0 + chunk*128;
        if (fullK){
            #pragma unroll
            for (int mt = 0; mt < 2; mt++)
                #pragma unroll
                for (int nt = 0; nt < 8; nt++)
                    #pragma unroll
                    for (int h = 0; h < 2; h++){
                        int slot = mt*2 + h;
                        float2 ef = exp2_pair(acc[mt][nt][h*2+0]*SC,
                                              acc[mt][nt][h*2+1]*SC);
                        sexp[slot] += ef.x + ef.y;
                    }
        } else {
            #pragma unroll
            for (int mt = 0; mt < 2; mt++){
                #pragma unroll
                for (int nt = 0; nt < 8; nt++){
                    int cbase = knChunk + n0 + nt*8 + tig*2;
                    #pragma unroll
                    for (int h = 0; h < 2; h++){
                        int slot = mt*2 + h;
                        float2 ef = exp2_pair(acc[mt][nt][h*2+0]*SC,
                                              acc[mt][nt][h*2+1]*SC);
                        if (cbase + 0 < Ksel) sexp[slot] += ef.x;
                        if (cbase + 1 < Ksel) sexp[slot] += ef.y;
                    }
                }
            }
        }
        if (more){
            __syncthreads();
            #pragma unroll
            for (int it = 0; it < 4; it++){
                int i = tid + it*256;
                int row = i >> 3, q = i & 7;
                *(uint4*)(sB + row*ROWB + q*16) = pref[it];
            }
            __syncthreads();
        }
    }
    #pragma unroll
    for (int s = 0; s < 4; s++){
        sexp[s] += __shfl_xor_sync(0xffffffffu, sexp[s], 1);
        sexp[s] += __shfl_xor_sync(0xffffffffu, sexp[s], 2);
    }
    if (tig == 0){
        #pragma unroll
        for (int s = 0; s < 4; s++){
            int lrow = m0 + (s >> 1)*16 + g + (s & 1)*8;
            redE[lrow][warpn] = sexp[s];
        }
    }
    __syncthreads();
    if (tid < 128){
        g_partLpp[b][sp][rt*128 + tid] = 0.f;
        g_partExp[b][sp][rt*128 + tid] = redE[tid][0] + redE[tid][1];
    }
}

// ------------------------- per-image loss + fused final output ---------------
__global__ void k_final(float* out, int B){
    int b = blockIdx.x, tid = threadIdx.x;
    int nposE = min(g_tot[b][0], PP);
    int npairs = nposE - 1;
    float sum = 0.f; int cnt = 0;
    if (npairs > 0){
        for (int r = tid; r < nposE; r += 256){
            float sl = 0.f, se = 0.f;
            #pragma unroll
            for (int sp = 0; sp < NSPLIT; sp++){ sl += g_partLpp[b][sp][r]; se += g_partExp[b][sp][r]; }
            sum += logf(se) - sl/(float)npairs;
            cnt++;
        }
    }
    __shared__ float ssum[256];
    __shared__ int scnt[256];
    ssum[tid] = sum; scnt[tid] = cnt;
    __syncthreads();
    for (int s = 128; s > 0; s >>= 1){
        if (tid < s){ ssum[tid] += ssum[tid+s]; scnt[tid] += scnt[tid+s]; }
        __syncthreads();
    }
    if (tid == 0){
        g_imgloss[b] = (scnt[0] > 0) ? ssum[0]/(float)scnt[0] : 0.f;
        g_has[b] = (scnt[0] > 0) ? 1 : 0;
        __threadfence();
        int t = atomicAdd(&g_done, 1);
        if (t == B-1){
            float s = 0.f; int c = 0;
            for (int bb = 0; bb < B; bb++) if (g_has[bb]){ s += g_imgloss[bb]; c++; }
            out[0] = s / (float)(c > 0 ? c : 1);
        }
    }
}

// ------------------------- launch -------------------------------------------
extern "C" void kernel_launch(void* const* d_in, const int* in_sizes, int n_in,
                              void* d_out, int out_size){
    const float* feat = (const float*)d_in[0];
    const long long* labels = (const long long*)d_in[1];
    int B = in_sizes[1] / HW;
    if (B < 1) B = 1; if (B > MAXB) B = MAXB;

    cudaFuncSetAttribute(k_simpp,  cudaFuncAttributeMaxDynamicSharedMemorySize, FUSE_SMEM);
    cudaFuncSetAttribute(k_lossPN, cudaFuncAttributeMaxDynamicSharedMemorySize, PN_SMEM);

    k_fgh    <<<dim3(Hh, B), 128>>>(labels);
    k_vrim   <<<dim3(NBLK, B), 256>>>();
    k_scan   <<<B, 32>>>();
    k_scatter<<<dim3(NBLK, B), 256>>>();
    int warps = B*(PP + KCc)/16;
    k_gather <<<(warps + 7)/8, 256>>>(feat, B);
    k_simpp  <<<dim3(16 + KCc/128, B), 256, FUSE_SMEM>>>();
    k_select <<<B, 1024>>>();
    k_lossPN <<<dim3(PP/128, NSPLIT-1, B), 256, PN_SMEM>>>();
    k_final  <<<B, 256>>>((float*)d_out, B);
}

// round 17
// speedup vs baseline: 1.0555x; 1.0082x over previous
#include <cuda_runtime.h>
#include <cuda_fp16.h>
#include <math.h>
#include <stdint.h>

// Problem constants (shapes fixed by setup_inputs)
#define Hh 384
#define Ww 384
#define HW (Hh*Ww)          // 147456
#define MAXB 4
#define CC 64               // channels
#define PP 2048             // max positives
#define KCc 20480           // rim candidate pool
#define KNn 10240           // max negatives
#define RAD 5               // dilation radius (kernel 11)
#define NBLK (HW/1024)      // 144 compaction blocks per image
#define NSPLIT 6
#define INV_T 10.0f

// ---- mma tile config ----
#define ROWB 144            // bytes per padded row (72 fp16): conflict-free frags
#define TILE_B (128*ROWB)   // 18432 bytes per tile buffer
// fused sim+pp kernel dynamic smem: 4 tiles
#define LS_AHI 0
#define LS_ALO (TILE_B)
#define LS_BHI (2*TILE_B)
#define LS_BLO (3*TILE_B)
#define FUSE_SMEM (4*TILE_B)           // 73728
// pn loss kernel: A + B
#define PN_SMEM (2*TILE_B)             // 36864

// ------------------------- scratch (device globals) -------------------------
__device__ unsigned char g_fg [MAXB][HW];
__device__ unsigned char g_hd [MAXB][HW];
__device__ unsigned char g_rim[MAXB][HW];
__device__ int   g_bcnt[MAXB][NBLK][2];
__device__ int   g_boff[MAXB][NBLK][2];
__device__ int   g_tot [MAXB][2];          // [0]=total fg, [1]=total rim
__device__ int   g_pidx[MAXB][PP];
__device__ int   g_cidx[MAXB][KCc];
__device__ __half g_pf_hi[MAXB][PP][CC];
__device__ __half g_pf_lo[MAXB][PP][CC];
__device__ __half g_cf_hi[MAXB][KCc][CC];
__device__ float g_maxsim[MAXB][KCc];
__device__ int   g_nsel[MAXB][KNn];
__device__ int   g_ksel[MAXB];
__device__ float g_partLpp[MAXB][NSPLIT][PP];
__device__ float g_partExp[MAXB][NSPLIT][PP];
__device__ float g_imgloss[MAXB];
__device__ int   g_has[MAXB];
__device__ int   g_done;

// ------------------------- asm helpers ---------------------------------------
__device__ __forceinline__ void mma_fp16(float* d, const uint32_t* a, const uint32_t* b){
    asm volatile(
        "mma.sync.aligned.m16n8k16.row.col.f32.f16.f16.f32 "
        "{%0,%1,%2,%3}, {%4,%5,%6,%7}, {%8,%9}, {%0,%1,%2,%3};"
        : "+f"(d[0]), "+f"(d[1]), "+f"(d[2]), "+f"(d[3])
        : "r"(a[0]), "r"(a[1]), "r"(a[2]), "r"(a[3]), "r"(b[0]), "r"(b[1]));
}
// zero-C variant: writes D fresh (no accumulator reset needed)
__device__ __forceinline__ void mma_fp16_z(float* d, const uint32_t* a, const uint32_t* b){
    asm volatile(
        "mma.sync.aligned.m16n8k16.row.col.f32.f16.f16.f32 "
        "{%0,%1,%2,%3}, {%4,%5,%6,%7}, {%8,%9}, {%10,%10,%10,%10};"
        : "=f"(d[0]), "=f"(d[1]), "=f"(d[2]), "=f"(d[3])
        : "r"(a[0]), "r"(a[1]), "r"(a[2]), "r"(a[3]), "r"(b[0]), "r"(b[1]),
          "f"(0.0f));
}
// paired 2^x on two half values in one MUFU op
__device__ __forceinline__ float2 exp2_pair(float x0, float x1){
    __half2 h = __floats2half2_rn(x0, x1);
    uint32_t hi = *(uint32_t*)&h, ho;
    asm("ex2.approx.f16x2 %0, %1;" : "=r"(ho) : "r"(hi));
    __half2 he = *(__half2*)&ho;
    return __half22float2(he);
}

// ------------------------- fused fg + horizontal dilation --------------------
__global__ void __launch_bounds__(128) k_fgh(const long long* __restrict__ labels){
    int b = blockIdx.y, row = blockIdx.x;
    int tid = threadIdx.x;
    __shared__ unsigned char srow[Ww];
    const long long* lab = labels + (size_t)b*HW + row*Ww;
    for (int i = tid; i < Ww; i += 128) srow[i] = (lab[i] > 0) ? 1 : 0;
    __syncthreads();
    unsigned char* fgr = &g_fg[b][row*Ww];
    unsigned char* hdr = &g_hd[b][row*Ww];
    for (int i = tid; i < Ww; i += 128){
        fgr[i] = srow[i];
        int lo = i-RAD; if (lo < 0) lo = 0;
        int hi = i+RAD; if (hi > Ww-1) hi = Ww-1;
        unsigned char m = 0;
        for (int c = lo; c <= hi; c++) m |= srow[c];
        hdr[i] = m;
    }
}

// ------------------------- fused vertical dilation + rim + count ------------
__global__ void __launch_bounds__(256) k_vrim(){
    int b = blockIdx.y, blk = blockIdx.x, tid = threadIdx.x;
    int base = blk*1024 + tid*4;
    int cf = 0, cr = 0;
    #pragma unroll
    for (int e = 0; e < 4; e++){
        int p = base + e;
        int row = p / Ww, col = p % Ww;
        int lo = row-RAD; if (lo < 0) lo = 0;
        int hi = row+RAD; if (hi > Hh-1) hi = Hh-1;
        unsigned char m = 0;
        for (int r = lo; r <= hi; r++) m |= g_hd[b][r*Ww + col];
        unsigned char fg = g_fg[b][p];
        unsigned char rim = (m && !fg) ? 1 : 0;
        g_rim[b][p] = rim;
        cf += fg; cr += rim;
    }
    __shared__ int sf, sr;
    if (tid == 0){ sf = 0; sr = 0; }
    __syncthreads();
    atomicAdd(&sf, cf); atomicAdd(&sr, cr);
    __syncthreads();
    if (tid == 0){ g_bcnt[b][blk][0] = sf; g_bcnt[b][blk][1] = sr; }
}

// ------------------------- scan (+ reset done counter) ----------------------
__global__ void k_scan(){
    int b = blockIdx.x;
    if (threadIdx.x == 0){
        if (b == 0) g_done = 0;
        int a0 = 0, a1 = 0;
        for (int k = 0; k < NBLK; k++){
            g_boff[b][k][0] = a0; a0 += g_bcnt[b][k][0];
            g_boff[b][k][1] = a1; a1 += g_bcnt[b][k][1];
        }
        g_tot[b][0] = a0; g_tot[b][1] = a1;
    }
}
__global__ void k_scatter(){
    int b = blockIdx.y, blk = blockIdx.x, tid = threadIdx.x;
    int base = blk*1024 + tid*4;
    unsigned char ff[4], rr[4];
    int lf = 0, lr = 0;
    #pragma unroll
    for (int e = 0; e < 4; e++){
        ff[e] = g_fg[b][base+e];  rr[e] = g_rim[b][base+e];
        lf += ff[e]; lr += rr[e];
    }
    __shared__ int sc[256];
    int own = lf | (lr << 16);
    sc[tid] = own;
    __syncthreads();
    for (int off = 1; off < 256; off <<= 1){
        int v = (tid >= off) ? sc[tid-off] : 0;
        __syncthreads();
        sc[tid] += v;
        __syncthreads();
    }
    int ex = sc[tid] - own;
    int offF = g_boff[b][blk][0] + (ex & 0xffff);
    int offR = g_boff[b][blk][1] + (ex >> 16);
    #pragma unroll
    for (int e = 0; e < 4; e++){
        if (ff[e]){ if (offF < PP)  g_pidx[b][offF] = base+e; offF++; }
        if (rr[e]){ if (offR < KCc) g_cidx[b][offR] = base+e; offR++; }
    }
}

// ------------------------- gather + L2 normalize -> fp16 hi/lo ---------------
// Warp = 8 slots x 4 channel-quarters (lane = quarter*8 + s). Each thread
// loads 16 channels; partial ss combined via two shfls. Quarters the
// per-thread latency chain vs the original 64-channel variant.
__global__ void __launch_bounds__(256) k_gather(const float* __restrict__ feat, int B){
    int gw = (blockIdx.x*blockDim.x + threadIdx.x) >> 5;
    int lane = threadIdx.x & 31;
    const int per = PP + KCc;           // 22528
    const int wpi = per/8;              // 2816 warps per image
    if (gw >= B*wpi) return;
    int b = gw / wpi;
    int ws = (gw % wpi)*8;
    int s = lane & 7;
    int quart = lane >> 3;              // 0..3 -> ch quart*16 .. +15
    int slot = ws + s;
    bool isP = (slot < PP);
    int lslot = isP ? slot : slot - PP;
    int cnt  = isP ? min(g_tot[b][0], PP) : min(g_tot[b][1], KCc);
    const int* idxArr = isP ? g_pidx[b] : g_cidx[b];
    bool valid = lslot < cnt;
    int pix = valid ? idxArr[lslot] : 0;
    const float* fp = feat + (size_t)b*CC*HW + (size_t)(quart*16)*HW + pix;
    float v[16];
    float ss = 0.f;
    #pragma unroll
    for (int c = 0; c < 16; c++){
        float x = __ldg(fp + (size_t)c*HW);
        v[c] = x;
        ss += x*x;
    }
    ss += __shfl_xor_sync(0xffffffffu, ss, 8);
    ss += __shfl_xor_sync(0xffffffffu, ss, 16);
    float inv = valid ? (1.f / fmaxf(sqrtf(ss), 1e-8f)) : 0.f;
    int cb = quart*16;
    if (isP){
        __half* dh = g_pf_hi[b][lslot] + cb;
        __half* dl = g_pf_lo[b][lslot] + cb;
        #pragma unroll
        for (int c = 0; c < 16; c += 2){
            float x0 = v[c]*inv, x1 = v[c+1]*inv;
            __half h0 = __float2half_rn(x0), h1 = __float2half_rn(x1);
            *(__half2*)(dh + c) = __halves2half2(h0, h1);
            *(__half2*)(dl + c) = __halves2half2(
                __float2half_rn(x0 - __half2float(h0)),
                __float2half_rn(x1 - __half2float(h1)));
        }
    } else {
        __half* dh = g_cf_hi[b][lslot] + cb;
        #pragma unroll
        for (int c = 0; c < 16; c += 2){
            float x0 = v[c]*inv, x1 = v[c+1]*inv;
            *(__half2*)(dh + c) = __halves2half2(__float2half_rn(x0), __float2half_rn(x1));
        }
    }
}

// ------------------------- fused: pp loss CTAs + mining CTAs ----------------
// blockIdx.x < 16  -> pp loss row-tile rt = blockIdx.x  (3-pass compensated)
// blockIdx.x >= 16 -> mining ct = blockIdx.x - 16 (1-pass, reg-prefetch,
//                     zero-C mma, fast-path epilogue)
__global__ void __launch_bounds__(256) k_simpp(){
    int b = blockIdx.y;
    int tid = threadIdx.x, wid = tid >> 5, lane = tid & 31;
    int warpm = wid & 3, warpn = wid >> 2;
    int g = lane >> 2, tig = lane & 3;
    extern __shared__ char sm[];
    int m0 = warpm*32, n0 = warpn*64;
    int nposE = min(g_tot[b][0], PP);

    if (blockIdx.x < 16){
        // ================= pp loss (split 0), 3-pass =================
        int rt = blockIdx.x;
        __shared__ float redL[128][2];
        __shared__ float redE[128][2];

        for (int i = tid; i < 128*8; i += 256){
            int row = i >> 3, q = i & 7;
            int slot = rt*128 + row;
            uint4 vh = make_uint4(0,0,0,0), vl = make_uint4(0,0,0,0);
            if (slot < nposE){
                vh = ((const uint4*)g_pf_hi[b][slot])[q];
                vl = ((const uint4*)g_pf_lo[b][slot])[q];
            }
            *(uint4*)(sm + LS_AHI + row*ROWB + q*16) = vh;
            *(uint4*)(sm + LS_ALO + row*ROWB + q*16) = vl;
        }

        float acc[2][8][4];
        #pragma unroll
        for (int mt = 0; mt < 2; mt++)
            #pragma unroll
            for (int nt = 0; nt < 8; nt++)
                #pragma unroll
                for (int r = 0; r < 4; r++) acc[mt][nt][r] = 0.f;
        float slpp[4] = {0.f,0.f,0.f,0.f};
        float sexp[4] = {0.f,0.f,0.f,0.f};

        for (int chunk = 0; chunk < 16; chunk++){
            int colBase = chunk*128;
            __syncthreads();
            for (int i = tid; i < 128*8; i += 256){
                int row = i >> 3, q = i & 7;
                int jg = colBase + row;
                uint4 vh = make_uint4(0,0,0,0), vl = make_uint4(0,0,0,0);
                if (jg < nposE){
                    vh = ((const uint4*)g_pf_hi[b][jg])[q];
                    vl = ((const uint4*)g_pf_lo[b][jg])[q];
                }
                *(uint4*)(sm + LS_BHI + row*ROWB + q*16) = vh;
                *(uint4*)(sm + LS_BLO + row*ROWB + q*16) = vl;
            }
            __syncthreads();
            #pragma unroll
            for (int ks = 0; ks < 4; ks++){
                int kb = ks*32 + tig*4;
                uint32_t Ah[2][4], Al[2][4];
                #pragma unroll
                for (int mt = 0; mt < 2; mt++){
                    int abase = (m0 + mt*16 + g)*ROWB + kb;
                    Ah[mt][0] = *(uint32_t*)(sm + LS_AHI + abase);
                    Ah[mt][1] = *(uint32_t*)(sm + LS_AHI + abase + 8*ROWB);
                    Ah[mt][2] = *(uint32_t*)(sm + LS_AHI + abase + 16);
                    Ah[mt][3] = *(uint32_t*)(sm + LS_AHI + abase + 8*ROWB + 16);
                    Al[mt][0] = *(uint32_t*)(sm + LS_ALO + abase);
                    Al[mt][1] = *(uint32_t*)(sm + LS_ALO + abase + 8*ROWB);
                    Al[mt][2] = *(uint32_t*)(sm + LS_ALO + abase + 16);
                    Al[mt][3] = *(uint32_t*)(sm + LS_ALO + abase + 8*ROWB + 16);
                }
                #pragma unroll
                for (int nt = 0; nt < 8; nt++){
                    int bbase = (n0 + nt*8 + g)*ROWB + kb;
                    uint32_t Bh[2], Bl[2];
                    Bh[0] = *(uint32_t*)(sm + LS_BHI + bbase);
                    Bh[1] = *(uint32_t*)(sm + LS_BHI + bbase + 16);
                    Bl[0] = *(uint32_t*)(sm + LS_BLO + bbase);
                    Bl[1] = *(uint32_t*)(sm + LS_BLO + bbase + 16);
                    #pragma unroll
                    for (int mt = 0; mt < 2; mt++){
                        mma_fp16(acc[mt][nt], Ah[mt], Bh);
                        mma_fp16(acc[mt][nt], Ah[mt], Bl);
                        mma_fp16(acc[mt][nt], Al[mt], Bh);
                    }
                }
            }
            #pragma unroll
            for (int mt = 0; mt < 2; mt++){
                #pragma unroll
                for (int nt = 0; nt < 8; nt++){
                    int cbase = colBase + n0 + nt*8 + tig*2;
                    #pragma unroll
                    for (int r = 0; r < 4; r++){
                        int jg = cbase + (r & 1);
                        int slot = mt*2 + (r >> 1);
                        int myrow = rt*128 + m0 + mt*16 + g + (r >> 1)*8;
                        float lp = acc[mt][nt][r] * INV_T;
                        if (jg < nposE && jg != myrow){
                            slpp[slot] += lp;
                            sexp[slot] += __expf(lp);
                        }
                        acc[mt][nt][r] = 0.f;
                    }
                }
            }
        }
        #pragma unroll
        for (int s = 0; s < 4; s++){
            slpp[s] += __shfl_xor_sync(0xffffffffu, slpp[s], 1);
            slpp[s] += __shfl_xor_sync(0xffffffffu, slpp[s], 2);
            sexp[s] += __shfl_xor_sync(0xffffffffu, sexp[s], 1);
            sexp[s] += __shfl_xor_sync(0xffffffffu, sexp[s], 2);
        }
        if (tig == 0){
            #pragma unroll
            for (int s = 0; s < 4; s++){
                int lrow = m0 + (s >> 1)*16 + g + (s & 1)*8;
                redL[lrow][warpn] = slpp[s];
                redE[lrow][warpn] = sexp[s];
            }
        }
        __syncthreads();
        if (tid < 128){
            g_partLpp[b][0][rt*128 + tid] = redL[tid][0] + redL[tid][1];
            g_partExp[b][0][rt*128 + tid] = redE[tid][0] + redE[tid][1];
        }
    } else {
        // ============ mining: reg-prefetch + zero-C mma + fast epilogue ============
        int ct = blockIdx.x - 16;
        char* sA = sm;
        char* sB = sm + TILE_B;
        __shared__ float redM[128][2];
        int ncandE = min(g_tot[b][1], KCc);
        bool fullP = (nposE == PP);

        // stage A once + B chunk0
        for (int i = tid; i < 128*8; i += 256){
            int row = i >> 3, q = i & 7;
            int slot = ct*128 + row;
            uint4 v = make_uint4(0,0,0,0);
            if (slot < ncandE) v = ((const uint4*)g_cf_hi[b][slot])[q];
            *(uint4*)(sA + row*ROWB + q*16) = v;
            uint4 v2 = make_uint4(0,0,0,0);
            if (row < nposE) v2 = ((const uint4*)g_pf_hi[b][row])[q];
            *(uint4*)(sB + row*ROWB + q*16) = v2;
        }
        __syncthreads();

        float acc[2][8][4];
        float rowmax[4] = {-INFINITY, -INFINITY, -INFINITY, -INFINITY};

        for (int chunk = 0; chunk < PP/128; chunk++){
            uint4 pref[4];
            bool more = (chunk + 1 < PP/128);
            if (more){
                #pragma unroll
                for (int it = 0; it < 4; it++){
                    int i = tid + it*256;
                    int row = i >> 3, q = i & 7;
                    int slot = (chunk+1)*128 + row;
                    pref[it] = make_uint4(0,0,0,0);
                    if (slot < nposE) pref[it] = ((const uint4*)g_pf_hi[b][slot])[q];
                }
            }
            #pragma unroll
            for (int ks = 0; ks < 4; ks++){
                int kb = ks*32 + tig*4;
                uint32_t Ah[2][4];
                #pragma unroll
                for (int mt = 0; mt < 2; mt++){
                    int abase = (m0 + mt*16 + g)*ROWB + kb;
                    Ah[mt][0] = *(uint32_t*)(sA + abase);
                    Ah[mt][1] = *(uint32_t*)(sA + abase + 8*ROWB);
                    Ah[mt][2] = *(uint32_t*)(sA + abase + 16);
                    Ah[mt][3] = *(uint32_t*)(sA + abase + 8*ROWB + 16);
                }
                #pragma unroll
                for (int nt = 0; nt < 8; nt++){
                    int bbase = (n0 + nt*8 + g)*ROWB + kb;
                    uint32_t Bh[2];
                    Bh[0] = *(uint32_t*)(sB + bbase);
                    Bh[1] = *(uint32_t*)(sB + bbase + 16);
                    #pragma unroll
                    for (int mt = 0; mt < 2; mt++){
                        if (ks == 0) mma_fp16_z(acc[mt][nt], Ah[mt], Bh);
                        else         mma_fp16  (acc[mt][nt], Ah[mt], Bh);
                    }
                }
            }
            int colChunk = chunk*128;
            if (fullP){
                #pragma unroll
                for (int mt = 0; mt < 2; mt++)
                    #pragma unroll
                    for (int nt = 0; nt < 8; nt++)
                        #pragma unroll
                        for (int r = 0; r < 4; r++){
                            int slot = mt*2 + (r >> 1);
                            rowmax[slot] = fmaxf(rowmax[slot], acc[mt][nt][r]);
                        }
            } else {
                #pragma unroll
                for (int mt = 0; mt < 2; mt++){
                    #pragma unroll
                    for (int nt = 0; nt < 8; nt++){
                        int cbase = colChunk + n0 + nt*8 + tig*2;
                        #pragma unroll
                        for (int r = 0; r < 4; r++){
                            int col = cbase + (r & 1);
                            if (col < nposE){
                                int slot = mt*2 + (r >> 1);
                                rowmax[slot] = fmaxf(rowmax[slot], acc[mt][nt][r]);
                            }
                        }
                    }
                }
            }
            if (more){
                __syncthreads();
                #pragma unroll
                for (int it = 0; it < 4; it++){
                    int i = tid + it*256;
                    int row = i >> 3, q = i & 7;
                    *(uint4*)(sB + row*ROWB + q*16) = pref[it];
                }
                __syncthreads();
            }
        }
        #pragma unroll
        for (int s = 0; s < 4; s++){
            rowmax[s] = fmaxf(rowmax[s], __shfl_xor_sync(0xffffffffu, rowmax[s], 1));
            rowmax[s] = fmaxf(rowmax[s], __shfl_xor_sync(0xffffffffu, rowmax[s], 2));
        }
        if (tig == 0){
            #pragma unroll
            for (int s = 0; s < 4; s++){
                int lrow = m0 + (s >> 1)*16 + g + (s & 1)*8;
                redM[lrow][warpn] = rowmax[s];
            }
        }
        __syncthreads();
        if (tid < 128){
            float m = fmaxf(redM[tid][0], redM[tid][1]);
            int slot = ct*128 + tid;
            g_maxsim[b][slot] = (slot < ncandE && nposE > 0) ? m : -INFINITY;
        }
    }
}

// ------------------------- radix top-K select (1024 thr) --------------------
__device__ __forceinline__ unsigned int simkey(int b, int c, int ncandE){
    float v = (c < ncandE) ? g_maxsim[b][c] : -INFINITY;
    unsigned int u = __float_as_uint(v);
    return (u & 0x80000000u) ? ~u : (u | 0x80000000u);
}
__global__ void __launch_bounds__(1024) k_select(){
    int b = blockIdx.x, tid = threadIdx.x;
    __shared__ int hist[256];
    __shared__ int sChosen, sRem;
    __shared__ int scg[1024], sce[1024];
    int nposE  = min(g_tot[b][0], PP);
    int ncandE = min(g_tot[b][1], KCc);
    int nallow = min(5*nposE, KNn);
    int Ksel = min(nallow, ncandE);
    if (nposE == 0) Ksel = 0;
    if (tid == 0) g_ksel[b] = Ksel;
    if (Ksel == 0) return;

    unsigned int prefix = 0, prefMask = 0;
    int remK = Ksel;
    for (int byte = 3; byte >= 0; byte--){
        if (tid < 256) hist[tid] = 0;
        __syncthreads();
        int shift = byte*8;
        for (int c = tid; c < KCc; c += 1024){
            unsigned int k = simkey(b, c, ncandE);
            if ((k & prefMask) == prefix) atomicAdd(&hist[(k >> shift) & 255], 1);
        }
        __syncthreads();
        if (tid == 0){
            int cum = 0, chosen = 0;
            for (int d = 255; d >= 0; d--){
                if (cum + hist[d] >= remK){ chosen = d; break; }
                cum += hist[d];
            }
            sChosen = chosen; sRem = remK - cum;
        }
        __syncthreads();
        prefix  |= ((unsigned int)sChosen) << shift;
        prefMask |= 0xFFu << shift;
        remK = sRem;
        __syncthreads();
    }
    unsigned int T = prefix;
    int begin = tid*20, end = begin + 20;
    int cg = 0, ce = 0;
    for (int c = begin; c < end; c++){
        unsigned int k = simkey(b, c, ncandE);
        if (k > T) cg++; else if (k == T) ce++;
    }
    scg[tid] = cg; sce[tid] = ce;
    __syncthreads();
    for (int off = 1; off < 1024; off <<= 1){
        int a1 = (tid >= off) ? scg[tid-off] : 0;
        int a2 = (tid >= off) ? sce[tid-off] : 0;
        __syncthreads();
        scg[tid] += a1; sce[tid] += a2;
        __syncthreads();
    }
    int gOff = scg[tid] - cg;
    int eOff = sce[tid] - ce;
    int count_gt = scg[1023];
    for (int c = begin; c < end; c++){
        unsigned int k = simkey(b, c, ncandE);
        if (k > T){ g_nsel[b][gOff++] = c; }
        else if (k == T){
            if (eOff < remK) g_nsel[b][count_gt + eOff] = c;
            eOff++;
        }
    }
}

// ------------------------- pn loss: reg-prefetch + paired exp + fast path ---
__global__ void __launch_bounds__(256) k_lossPN(){
    int b = blockIdx.z, rt = blockIdx.x, sp = 1 + blockIdx.y;
    int tid = threadIdx.x, wid = tid >> 5, lane = tid & 31;
    int warpm = wid & 3, warpn = wid >> 2;
    int g = lane >> 2, tig = lane & 3;
    extern __shared__ char sm[];
    char* sA = sm;
    char* sB = sm + TILE_B;
    __shared__ float redE[128][2];
    int nposE = min(g_tot[b][0], PP);
    int Ksel  = g_ksel[b];
    int knBase0 = sp*2048 - PP;
    const float SC = INV_T * 1.44269504f;   // fold temperature into log2e
    bool fullK = (Ksel == KNn);

    // stage A + B chunk0
    for (int i = tid; i < 128*8; i += 256){
        int row = i >> 3, q = i & 7;
        int slot = rt*128 + row;
        uint4 vh = make_uint4(0,0,0,0);
        if (slot < nposE) vh = ((const uint4*)g_pf_hi[b][slot])[q];
        *(uint4*)(sA + row*ROWB + q*16) = vh;
        int kn = knBase0 + row;
        uint4 v2 = make_uint4(0,0,0,0);
        if (kn < Ksel) v2 = ((const uint4*)g_cf_hi[b][g_nsel[b][kn]])[q];
        *(uint4*)(sB + row*ROWB + q*16) = v2;
    }
    __syncthreads();

    float acc[2][8][4];
    float sexp[4] = {0.f,0.f,0.f,0.f};

    int m0 = warpm*32, n0 = warpn*64;
    for (int chunk = 0; chunk < 16; chunk++){
        uint4 pref[4];
        bool more = (chunk + 1 < 16);
        if (more){
            int knB = knBase0 + (chunk+1)*128;
            #pragma unroll
            for (int it = 0; it < 4; it++){
                int i = tid + it*256;
                int row = i >> 3, q = i & 7;
                int kn = knB + row;
                pref[it] = make_uint4(0,0,0,0);
                if (kn < Ksel) pref[it] = ((const uint4*)g_cf_hi[b][g_nsel[b][kn]])[q];
            }
        }
        #pragma unroll
        for (int ks = 0; ks < 4; ks++){
            int kb = ks*32 + tig*4;
            uint32_t Ah[2][4];
            #pragma unroll
            for (int mt = 0; mt < 2; mt++){
                int abase = (m0 + mt*16 + g)*ROWB + kb;
                Ah[mt][0] = *(uint32_t*)(sA + abase);
                Ah[mt][1] = *(uint32_t*)(sA + abase + 8*ROWB);
                Ah[mt][2] = *(uint32_t*)(sA + abase + 16);
                Ah[mt][3] = *(uint32_t*)(sA + abase + 8*ROWB + 16);
            }
            #pragma unroll
            for (int nt = 0; nt < 8; nt++){
                int bbase = (n0 + nt*8 + g)*ROWB + kb;
                uint32_t Bh[2];
                Bh[0] = *(uint32_t*)(sB + bbase);
                Bh[1] = *(uint32_t*)(sB + bbase + 16);
                #pragma unroll
                for (int mt = 0; mt < 2; mt++){
                    if (ks == 0) mma_fp16_z(acc[mt][nt], Ah[mt], Bh);
                    else         mma_fp16  (acc[mt][nt], Ah[mt], Bh);
                }
            }
        }
        int knChunk = knBase0 + chunk*128;
        if (fullK){
            #pragma unroll
            for (int mt = 0; mt < 2; mt++)
                #pragma unroll
                for (int nt = 0; nt < 8; nt++)
                    #pragma unroll
                    for (int h = 0; h < 2; h++){
                        int slot = mt*2 + h;
                        float2 ef = exp2_pair(acc[mt][nt][h*2+0]*SC,
                                              acc[mt][nt][h*2+1]*SC);
                        sexp[slot] += ef.x + ef.y;
                    }
        } else {
            #pragma unroll
            for (int mt = 0; mt < 2; mt++){
                #pragma unroll
                for (int nt = 0; nt < 8; nt++){
                    int cbase = knChunk + n0 + nt*8 + tig*2;
                    #pragma unroll
                    for (int h = 0; h < 2; h++){
                        int slot = mt*2 + h;
                        float2 ef = exp2_pair(acc[mt][nt][h*2+0]*SC,
                                              acc[mt][nt][h*2+1]*SC);
                        if (cbase + 0 < Ksel) sexp[slot] += ef.x;
                        if (cbase + 1 < Ksel) sexp[slot] += ef.y;
                    }
                }
            }
        }
        if (more){
            __syncthreads();
            #pragma unroll
            for (int it = 0; it < 4; it++){
                int i = tid + it*256;
                int row = i >> 3, q = i & 7;
                *(uint4*)(sB + row*ROWB + q*16) = pref[it];
            }
            __syncthreads();
        }
    }
    #pragma unroll
    for (int s = 0; s < 4; s++){
        sexp[s] += __shfl_xor_sync(0xffffffffu, sexp[s], 1);
        sexp[s] += __shfl_xor_sync(0xffffffffu, sexp[s], 2);
    }
    if (tig == 0){
        #pragma unroll
        for (int s = 0; s < 4; s++){
            int lrow = m0 + (s >> 1)*16 + g + (s & 1)*8;
            redE[lrow][warpn] = sexp[s];
        }
    }
    __syncthreads();
    if (tid < 128){
        g_partLpp[b][sp][rt*128 + tid] = 0.f;
        g_partExp[b][sp][rt*128 + tid] = redE[tid][0] + redE[tid][1];
    }
}

// ------------------------- per-image loss + fused final output ---------------
__global__ void k_final(float* out, int B){
    int b = blockIdx.x, tid = threadIdx.x;
    int nposE = min(g_tot[b][0], PP);
    int npairs = nposE - 1;
    float sum = 0.f; int cnt = 0;
    if (npairs > 0){
        for (int r = tid; r < nposE; r += 256){
            float sl = 0.f, se = 0.f;
            #pragma unroll
            for (int sp = 0; sp < NSPLIT; sp++){ sl += g_partLpp[b][sp][r]; se += g_partExp[b][sp][r]; }
            sum += logf(se) - sl/(float)npairs;
            cnt++;
        }
    }
    __shared__ float ssum[256];
    __shared__ int scnt[256];
    ssum[tid] = sum; scnt[tid] = cnt;
    __syncthreads();
    for (int s = 128; s > 0; s >>= 1){
        if (tid < s){ ssum[tid] += ssum[tid+s]; scnt[tid] += scnt[tid+s]; }
        __syncthreads();
    }
    if (tid == 0){
        g_imgloss[b] = (scnt[0] > 0) ? ssum[0]/(float)scnt[0] : 0.f;
        g_has[b] = (scnt[0] > 0) ? 1 : 0;
        __threadfence();
        int t = atomicAdd(&g_done, 1);
        if (t == B-1){
            float s = 0.f; int c = 0;
            for (int bb = 0; bb < B; bb++) if (g_has[bb]){ s += g_imgloss[bb]; c++; }
            out[0] = s / (float)(c > 0 ? c : 1);
        }
    }
}

// ------------------------- launch -------------------------------------------
extern "C" void kernel_launch(void* const* d_in, const int* in_sizes, int n_in,
                              void* d_out, int out_size){
    const float* feat = (const float*)d_in[0];
    const long long* labels = (const long long*)d_in[1];
    int B = in_sizes[1] / HW;
    if (B < 1) B = 1; if (B > MAXB) B = MAXB;

    cudaFuncSetAttribute(k_simpp,  cudaFuncAttributeMaxDynamicSharedMemorySize, FUSE_SMEM);
    cudaFuncSetAttribute(k_lossPN, cudaFuncAttributeMaxDynamicSharedMemorySize, PN_SMEM);

    k_fgh    <<<dim3(Hh, B), 128>>>(labels);
    k_vrim   <<<dim3(NBLK, B), 256>>>();
    k_scan   <<<B, 32>>>();
    k_scatter<<<dim3(NBLK, B), 256>>>();
    int warps = B*(PP + KCc)/8;
    k_gather <<<(warps + 7)/8, 256>>>(feat, B);
    k_simpp  <<<dim3(16 + KCc/128, B), 256, FUSE_SMEM>>>();
    k_select <<<B, 1024>>>();
    k_lossPN <<<dim3(PP/128, NSPLIT-1, B), 256, PN_SMEM>>>();
    k_final  <<<B, 256>>>((float*)d_out, B);
}